// round 5
// baseline (speedup 1.0000x reference)
#include <cuda_runtime.h>
#include <cstdint>

#define NROWS 8192
#define DIM 128

// Static scratch (allocation-free per harness rules)
__device__ float g_dis[NROWS];              // rsqrt(rowsum(A)+1)
__device__ float g_z[(size_t)NROWS * DIM];  // G[j][n] = dis_j*(X W^T)[j][n], tf32-rounded (k-major)

static __device__ __forceinline__ uint32_t s2u(const void* p) {
    uint32_t a;
    asm("{ .reg .u64 t; cvta.to.shared.u64 t, %1; cvt.u32.u64 %0, t; }" : "=r"(a) : "l"(p));
    return a;
}

// ===================== kernel 1: row sums -> dis =====================
__global__ void __launch_bounds__(256) rowsum_kernel(const float4* __restrict__ A4) {
    int row = blockIdx.x;
    const float4* r = A4 + (size_t)row * (NROWS / 4);
    float s = 0.f;
    #pragma unroll
    for (int p = 0; p < 8; p++) {
        float4 v = __ldcs(r + threadIdx.x + p * 256);
        s += (v.x + v.y) + (v.z + v.w);
    }
    #pragma unroll
    for (int o = 16; o; o >>= 1) s += __shfl_xor_sync(0xffffffffu, s, o);
    __shared__ float ws[8];
    if ((threadIdx.x & 31) == 0) ws[threadIdx.x >> 5] = s;
    __syncthreads();
    if (threadIdx.x < 8) {
        float t = ws[threadIdx.x];
        #pragma unroll
        for (int o = 4; o; o >>= 1) t += __shfl_xor_sync(0xffu, t, o);
        if (threadIdx.x == 0) g_dis[row] = rsqrtf(t + 1.0f);
    }
}

// ===================== kernel 2: G[j][n] = dis_j * (X W^T), tf32-rounded, k-major =====================
__global__ void __launch_bounds__(256) z_kernel(const float* __restrict__ X,
                                                const float* __restrict__ W) {
    __shared__ float4 Xs4[32 * 32];
    int tid = threadIdx.x;
    int j0 = blockIdx.x * 32;
    const float4* Xg = reinterpret_cast<const float4*>(X) + (size_t)j0 * 32;
    for (int i = tid; i < 1024; i += 256) Xs4[i] = Xg[i];
    __syncthreads();

    int n = tid & 127, half = tid >> 7;
    float acc[16];
    #pragma unroll
    for (int jj = 0; jj < 16; jj++) acc[jj] = 0.f;

    const float4* Wr = reinterpret_cast<const float4*>(W) + (size_t)n * 32;
    #pragma unroll 4
    for (int c4 = 0; c4 < 32; c4++) {
        float4 w = __ldg(Wr + c4);
        #pragma unroll
        for (int jj = 0; jj < 16; jj++) {
            float4 x = Xs4[(half * 16 + jj) * 32 + c4];
            acc[jj] += x.x * w.x + x.y * w.y + x.z * w.z + x.w * w.w;
        }
    }
    #pragma unroll
    for (int jj = 0; jj < 16; jj++) {
        int j = j0 + half * 16 + jj;
        float z = g_dis[j] * acc[jj];
        unsigned zb;
        asm("cvt.rna.tf32.f32 %0, %1;" : "=r"(zb) : "f"(z));
        g_z[(size_t)j * DIM + n] = __uint_as_float(zb);
    }
}

// ===================== kernel 3: fused GEMM: out = dis .* (A @ G + G) + b =====================
#define BM 64
#define BK 64
#define STG 4
#define ASTR 68                       // 64 k-floats + 4 pad: ldsm rows hit distinct banks
#define ASTG (BM * ASTR)              // 4352 floats per stage
#define SMEM_BYTES (STG * ASTG * 4)   // 69632 B

static __device__ __forceinline__ void mma_tf32(float* c, const uint32_t* a, const uint32_t* b) {
    asm volatile(
        "mma.sync.aligned.m16n8k8.row.col.f32.tf32.tf32.f32 "
        "{%0,%1,%2,%3}, {%4,%5,%6,%7}, {%8,%9}, {%0,%1,%2,%3};"
        : "+f"(c[0]), "+f"(c[1]), "+f"(c[2]), "+f"(c[3])
        : "r"(a[0]), "r"(a[1]), "r"(a[2]), "r"(a[3]), "r"(b[0]), "r"(b[1]));
}

static __device__ __forceinline__ void ldsm4(uint32_t* r, uint32_t addr) {
    asm volatile("ldmatrix.sync.aligned.m8n8.x4.shared.b16 {%0,%1,%2,%3}, [%4];"
                 : "=r"(r[0]), "=r"(r[1]), "=r"(r[2]), "=r"(r[3]) : "r"(addr));
}

__global__ void __launch_bounds__(256) gemm_kernel(const float* __restrict__ A,
                                                   const float* __restrict__ bias,
                                                   float* __restrict__ out) {
    extern __shared__ float sm[];
    float* sA = sm;                   // [STG][ASTG], A k-major rows

    int tid = threadIdx.x, wid = tid >> 5, lane = tid & 31;
    int gid = lane >> 2, tig = lane & 3;
    const int m0 = blockIdx.x * BM;

    // 8 warps: 2 m-groups x 4 n-groups; warp tile 32x32
    const int wm0 = (wid & 1) * 32, wn0 = (wid >> 1) * 32;

    float acc[2][4][4];
    #pragma unroll
    for (int mf = 0; mf < 2; mf++)
        #pragma unroll
        for (int nf = 0; nf < 4; nf++)
            #pragma unroll
            for (int q = 0; q < 4; q++) acc[mf][nf][q] = 0.f;

    // ldmatrix lane->address mapping
    const int lrow = lane & 15;           // row within 16
    const int ksel = (lane >> 4) * 4;     // k sub-offset 0 or 4

    // B fragment source: k-major g_z, L2-resident
    const float* Bp = g_z + wn0 + gid;    // + (k)*DIM + nf*8 later

    // cp.async one A stage: 64 rows x 64 k = 1024 float4, 4 per thread
    auto issue = [&](int stage, int buf) {
        int kk = stage * BK;
        #pragma unroll
        for (int it = 0; it < 4; it++) {
            int idx = it * 256 + tid;
            int r = idx >> 4, c4 = idx & 15;
            const float* gp = A + (size_t)(m0 + r) * NROWS + kk + c4 * 4;
            uint32_t sa = s2u(sA + buf * ASTG + r * ASTR + c4 * 4);
            asm volatile("cp.async.cg.shared.global [%0], [%1], 16;" :: "r"(sa), "l"(gp));
        }
        asm volatile("cp.async.commit_group;");
    };

    #pragma unroll
    for (int s = 0; s < STG - 1; s++) issue(s, s);

    const int NS = NROWS / BK;  // 128
    for (int i = 0; i < NS; i++) {
        asm volatile("cp.async.wait_group %0;" :: "n"(STG - 2));
        __syncthreads();
        if (i + STG - 1 < NS) issue(i + STG - 1, (i + STG - 1) & (STG - 1));

        uint32_t a_s = s2u(sA + (i & (STG - 1)) * ASTG);
        const float* Bk = Bp + (size_t)(i * BK) * DIM;

        #pragma unroll
        for (int ks = 0; ks < BK / 8; ks++) {
            int k0 = ks * 8;
            uint32_t ar[2][4];
            #pragma unroll
            for (int mf = 0; mf < 2; mf++)
                ldsm4(ar[mf], a_s + 4u * ((wm0 + mf * 16 + lrow) * ASTR + k0 + ksel));

            uint32_t br[4][2];
            const float* Bkk = Bk + (size_t)(k0 + tig) * DIM;
            #pragma unroll
            for (int nf = 0; nf < 4; nf++) {
                br[nf][0] = __float_as_uint(__ldg(Bkk + nf * 8));
                br[nf][1] = __float_as_uint(__ldg(Bkk + 4 * DIM + nf * 8));
            }
            #pragma unroll
            for (int mf = 0; mf < 2; mf++)
                #pragma unroll
                for (int nf = 0; nf < 4; nf++)
                    mma_tf32(acc[mf][nf], ar[mf], br[nf]);
        }
    }

    // fused epilogue: out = dis .* (acc + G) + bias
    #pragma unroll
    for (int mf = 0; mf < 2; mf++) {
        int r0 = m0 + wm0 + mf * 16 + gid;
        float d0 = g_dis[r0], d1 = g_dis[r0 + 8];
        #pragma unroll
        for (int nf = 0; nf < 4; nf++) {
            int c = wn0 + nf * 8 + 2 * tig;
            float2 bb = __ldg(reinterpret_cast<const float2*>(bias + c));
            float2 gz0 = *reinterpret_cast<const float2*>(&g_z[(size_t)r0 * DIM + c]);
            float2 gz1 = *reinterpret_cast<const float2*>(&g_z[(size_t)(r0 + 8) * DIM + c]);
            float2 o0, o1;
            o0.x = d0 * (acc[mf][nf][0] + gz0.x) + bb.x;
            o0.y = d0 * (acc[mf][nf][1] + gz0.y) + bb.y;
            o1.x = d1 * (acc[mf][nf][2] + gz1.x) + bb.x;
            o1.y = d1 * (acc[mf][nf][3] + gz1.y) + bb.y;
            *reinterpret_cast<float2*>(&out[(size_t)r0 * DIM + c]) = o0;
            *reinterpret_cast<float2*>(&out[(size_t)(r0 + 8) * DIM + c]) = o1;
        }
    }
}

// ===================== host =====================
extern "C" void kernel_launch(void* const* d_in, const int* in_sizes, int n_in,
                              void* d_out, int out_size) {
    const float* X = (const float*)d_in[0];
    const float* A = (const float*)d_in[1];
    const float* W = (const float*)d_in[2];
    const float* b = (const float*)d_in[3];
    float* out = (float*)d_out;

    rowsum_kernel<<<NROWS, 256>>>((const float4*)A);
    z_kernel<<<NROWS / 32, 256>>>(X, W);

    cudaFuncSetAttribute(gemm_kernel, cudaFuncAttributeMaxDynamicSharedMemorySize, SMEM_BYTES);
    gemm_kernel<<<NROWS / BM, 256, SMEM_BYTES>>>(A, b, out);
}

// round 6
// speedup vs baseline: 2.1927x; 2.1927x over previous
#include <cuda_runtime.h>
#include <cstdint>

#define NROWS 8192
#define DIM 128

// Static scratch (allocation-free per harness rules)
__device__ float g_dis[NROWS];                 // rsqrt(rowsum(A)+1)
__device__ float g_zt[(size_t)DIM * NROWS];    // G^T[n][j] = dis_j*(X W^T)[j][n], tf32-rounded

static __device__ __forceinline__ uint32_t s2u(const void* p) {
    uint32_t a;
    asm("{ .reg .u64 t; cvta.to.shared.u64 t, %1; cvt.u32.u64 %0, t; }" : "=r"(a) : "l"(p));
    return a;
}

// ===================== kernel 1: row sums -> dis =====================
__global__ void __launch_bounds__(256) rowsum_kernel(const float4* __restrict__ A4) {
    int row = blockIdx.x;
    const float4* r = A4 + (size_t)row * (NROWS / 4);
    float s = 0.f;
    #pragma unroll
    for (int p = 0; p < 8; p++) {
        float4 v = __ldcs(r + threadIdx.x + p * 256);
        s += (v.x + v.y) + (v.z + v.w);
    }
    #pragma unroll
    for (int o = 16; o; o >>= 1) s += __shfl_xor_sync(0xffffffffu, s, o);
    __shared__ float ws[8];
    if ((threadIdx.x & 31) == 0) ws[threadIdx.x >> 5] = s;
    __syncthreads();
    if (threadIdx.x < 8) {
        float t = ws[threadIdx.x];
        #pragma unroll
        for (int o = 4; o; o >>= 1) t += __shfl_xor_sync(0xffu, t, o);
        if (threadIdx.x == 0) g_dis[row] = rsqrtf(t + 1.0f);
    }
}

// ===================== kernel 2: G^T[n][j] = dis_j*(X W^T)[j][n], tf32-rounded =====================
__global__ void __launch_bounds__(256) z_kernel(const float* __restrict__ X,
                                                const float* __restrict__ W) {
    __shared__ float4 Xs4[32 * 32];       // 32 rows x 128 floats
    __shared__ float T[128][33];          // transpose staging
    int tid = threadIdx.x;
    int j0 = blockIdx.x * 32;
    const float4* Xg = reinterpret_cast<const float4*>(X) + (size_t)j0 * 32;
    for (int i = tid; i < 1024; i += 256) Xs4[i] = Xg[i];
    __syncthreads();

    int n = tid & 127, half = tid >> 7;
    float acc[16];
    #pragma unroll
    for (int jj = 0; jj < 16; jj++) acc[jj] = 0.f;

    const float4* Wr = reinterpret_cast<const float4*>(W) + (size_t)n * 32;
    #pragma unroll 4
    for (int c4 = 0; c4 < 32; c4++) {
        float4 w = __ldg(Wr + c4);
        #pragma unroll
        for (int jj = 0; jj < 16; jj++) {
            float4 x = Xs4[(half * 16 + jj) * 32 + c4];
            acc[jj] += x.x * w.x + x.y * w.y + x.z * w.z + x.w * w.w;
        }
    }
    #pragma unroll
    for (int jj = 0; jj < 16; jj++) {
        int j = j0 + half * 16 + jj;
        float z = g_dis[j] * acc[jj];
        unsigned zb;
        asm("cvt.rna.tf32.f32 %0, %1;" : "=r"(zb) : "f"(z));
        T[n][half * 16 + jj] = __uint_as_float(zb);
    }
    __syncthreads();
    #pragma unroll
    for (int it = 0; it < 4; it++) {
        int idx = it * 256 + tid;
        int nn = idx >> 3, j4 = idx & 7;
        float4 v = make_float4(T[nn][j4 * 4], T[nn][j4 * 4 + 1], T[nn][j4 * 4 + 2], T[nn][j4 * 4 + 3]);
        *reinterpret_cast<float4*>(&g_zt[(size_t)nn * NROWS + j0 + j4 * 4]) = v;
    }
}

// ===================== kernel 3: fused GEMM: out = dis .* (A @ G + G) + b =====================
#define BM 64
#define BK 32
#define STG 4
#define ASTR 36
#define BSTR 36
#define ASTG (BM * ASTR)              // 2304 floats
#define BSTG (DIM * BSTR)             // 4608 floats
#define SMEM_BYTES (STG * (ASTG + BSTG) * 4)   // 110592 B

static __device__ __forceinline__ void mma_tf32(float* c, const uint32_t* a, const uint32_t* b) {
    asm volatile(
        "mma.sync.aligned.m16n8k8.row.col.f32.tf32.tf32.f32 "
        "{%0,%1,%2,%3}, {%4,%5,%6,%7}, {%8,%9}, {%0,%1,%2,%3};"
        : "+f"(c[0]), "+f"(c[1]), "+f"(c[2]), "+f"(c[3])
        : "r"(a[0]), "r"(a[1]), "r"(a[2]), "r"(a[3]), "r"(b[0]), "r"(b[1]));
}

static __device__ __forceinline__ void ldsm4(uint32_t* r, uint32_t addr) {
    asm volatile("ldmatrix.sync.aligned.m8n8.x4.shared.b16 {%0,%1,%2,%3}, [%4];"
                 : "=r"(r[0]), "=r"(r[1]), "=r"(r[2]), "=r"(r[3]) : "r"(addr));
}

__global__ void __launch_bounds__(256) gemm_kernel(const float* __restrict__ A,
                                                   const float* __restrict__ bias,
                                                   float* __restrict__ out) {
    extern __shared__ float sm[];
    float* sA = sm;                   // [STG][ASTG] A: 64 m-rows x BK k (k-major)
    float* sB = sm + STG * ASTG;      // [STG][BSTG] B: 128 n-rows x BK k (g_zt layout)

    int tid = threadIdx.x, wid = tid >> 5, lane = tid & 31;
    int gid = lane >> 2, tig = lane & 3;
    const int m0 = blockIdx.x * BM;

    // 8 warps: 2 m-groups x 4 n-groups; warp tile 32x32
    const int wm0 = (wid & 1) * 32, wn0 = (wid >> 1) * 32;

    float acc[2][4][4];
    #pragma unroll
    for (int mf = 0; mf < 2; mf++)
        #pragma unroll
        for (int nf = 0; nf < 4; nf++)
            #pragma unroll
            for (int q = 0; q < 4; q++) acc[mf][nf][q] = 0.f;

    const int lrow = lane & 15;           // ldmatrix row within 16
    const int ksel = (lane >> 4) * 4;     // k sub-offset 0 or 4

    auto issue = [&](int stage, int buf) {
        int kk = stage * BK;
        #pragma unroll
        for (int it = 0; it < 2; it++) {               // A: 64 rows x 8 float4 = 512
            int idx = it * 256 + tid;
            int r = idx >> 3, c4 = idx & 7;
            const float* gp = A + (size_t)(m0 + r) * NROWS + kk + c4 * 4;
            uint32_t sa = s2u(sA + buf * ASTG + r * ASTR + c4 * 4);
            asm volatile("cp.async.cg.shared.global [%0], [%1], 16;" :: "r"(sa), "l"(gp));
        }
        #pragma unroll
        for (int it = 0; it < 4; it++) {               // B: 128 n-rows x 8 float4 = 1024
            int idx = it * 256 + tid;
            int r = idx >> 3, c4 = idx & 7;
            const float* gp = g_zt + (size_t)r * NROWS + kk + c4 * 4;
            uint32_t sb = s2u(sB + buf * BSTG + r * BSTR + c4 * 4);
            asm volatile("cp.async.cg.shared.global [%0], [%1], 16;" :: "r"(sb), "l"(gp));
        }
        asm volatile("cp.async.commit_group;");
    };

    #pragma unroll
    for (int s = 0; s < STG - 1; s++) issue(s, s);

    const int NS = NROWS / BK;  // 256
    for (int i = 0; i < NS; i++) {
        asm volatile("cp.async.wait_group %0;" :: "n"(STG - 2));
        __syncthreads();
        if (i + STG - 1 < NS) issue(i + STG - 1, (i + STG - 1) & (STG - 1));

        uint32_t a_s = s2u(sA + (i & (STG - 1)) * ASTG);
        uint32_t b_s = s2u(sB + (i & (STG - 1)) * BSTG);

        #pragma unroll
        for (int ks = 0; ks < BK / 8; ks++) {
            int k0 = ks * 8;
            uint32_t ar[2][4], br[2][4];
            #pragma unroll
            for (int mf = 0; mf < 2; mf++)
                ldsm4(ar[mf], a_s + 4u * ((wm0 + mf * 16 + lrow) * ASTR + k0 + ksel));
            #pragma unroll
            for (int p = 0; p < 2; p++)
                ldsm4(br[p], b_s + 4u * ((wn0 + p * 16 + lrow) * BSTR + k0 + ksel));
            #pragma unroll
            for (int mf = 0; mf < 2; mf++)
                #pragma unroll
                for (int p = 0; p < 2; p++) {
                    uint32_t b0[2] = {br[p][0], br[p][2]};
                    uint32_t b1[2] = {br[p][1], br[p][3]};
                    mma_tf32(acc[mf][2 * p], ar[mf], b0);
                    mma_tf32(acc[mf][2 * p + 1], ar[mf], b1);
                }
        }
    }

    // fused epilogue: out = dis .* (acc + G) + bias
    #pragma unroll
    for (int mf = 0; mf < 2; mf++) {
        int r0 = m0 + wm0 + mf * 16 + gid;
        float d0 = g_dis[r0], d1 = g_dis[r0 + 8];
        #pragma unroll
        for (int nf = 0; nf < 4; nf++) {
            int c = wn0 + nf * 8 + 2 * tig;
            float2 bb = __ldg(reinterpret_cast<const float2*>(bias + c));
            float gz00 = g_zt[(size_t)c * NROWS + r0];
            float gz01 = g_zt[(size_t)(c + 1) * NROWS + r0];
            float gz10 = g_zt[(size_t)c * NROWS + r0 + 8];
            float gz11 = g_zt[(size_t)(c + 1) * NROWS + r0 + 8];
            float2 o0, o1;
            o0.x = d0 * (acc[mf][nf][0] + gz00) + bb.x;
            o0.y = d0 * (acc[mf][nf][1] + gz01) + bb.y;
            o1.x = d1 * (acc[mf][nf][2] + gz10) + bb.x;
            o1.y = d1 * (acc[mf][nf][3] + gz11) + bb.y;
            *reinterpret_cast<float2*>(&out[(size_t)r0 * DIM + c]) = o0;
            *reinterpret_cast<float2*>(&out[(size_t)(r0 + 8) * DIM + c]) = o1;
        }
    }
}

// ===================== host =====================
extern "C" void kernel_launch(void* const* d_in, const int* in_sizes, int n_in,
                              void* d_out, int out_size) {
    const float* X = (const float*)d_in[0];
    const float* A = (const float*)d_in[1];
    const float* W = (const float*)d_in[2];
    const float* b = (const float*)d_in[3];
    float* out = (float*)d_out;

    rowsum_kernel<<<NROWS, 256>>>((const float4*)A);
    z_kernel<<<NROWS / 32, 256>>>(X, W);

    cudaFuncSetAttribute(gemm_kernel, cudaFuncAttributeMaxDynamicSharedMemorySize, SMEM_BYTES);
    gemm_kernel<<<NROWS / BM, 256, SMEM_BYTES>>>(A, b, out);
}

// round 7
// speedup vs baseline: 2.7342x; 1.2470x over previous
#include <cuda_runtime.h>
#include <cstdint>

#define NROWS 8192
#define DIM 128
#define KSPLIT 4
#define KSLICE (NROWS / KSPLIT)   // 2048

// Static scratch (allocation-free per harness rules)
__device__ float g_dis[NROWS];                        // rsqrt(rowsum(A)+1)
__device__ float g_z[(size_t)NROWS * DIM];            // G[j][n] k-major (for reduce)
__device__ float g_zt[(size_t)DIM * NROWS];           // G^T[n][j] n-major (GEMM B operand)
__device__ float g_part[KSPLIT][(size_t)NROWS * DIM]; // split-K partials

static __device__ __forceinline__ uint32_t s2u(const void* p) {
    uint32_t a;
    asm("{ .reg .u64 t; cvta.to.shared.u64 t, %1; cvt.u32.u64 %0, t; }" : "=r"(a) : "l"(p));
    return a;
}

// ===================== kernel 1: row sums -> dis =====================
__global__ void __launch_bounds__(256) rowsum_kernel(const float4* __restrict__ A4) {
    int row = blockIdx.x;
    const float4* r = A4 + (size_t)row * (NROWS / 4);
    float s = 0.f;
    #pragma unroll
    for (int p = 0; p < 8; p++) {
        float4 v = __ldcs(r + threadIdx.x + p * 256);
        s += (v.x + v.y) + (v.z + v.w);
    }
    #pragma unroll
    for (int o = 16; o; o >>= 1) s += __shfl_xor_sync(0xffffffffu, s, o);
    __shared__ float ws[8];
    if ((threadIdx.x & 31) == 0) ws[threadIdx.x >> 5] = s;
    __syncthreads();
    if (threadIdx.x < 8) {
        float t = ws[threadIdx.x];
        #pragma unroll
        for (int o = 4; o; o >>= 1) t += __shfl_xor_sync(0xffu, t, o);
        if (threadIdx.x == 0) g_dis[row] = rsqrtf(t + 1.0f);
    }
}

// ===================== kernel 2: G = dis.*(X W^T), tf32-rounded, BOTH layouts =====================
__global__ void __launch_bounds__(256) z_kernel(const float* __restrict__ X,
                                                const float* __restrict__ W) {
    __shared__ float4 Xs4[32 * 32];
    __shared__ float T[128][33];
    int tid = threadIdx.x;
    int j0 = blockIdx.x * 32;
    const float4* Xg = reinterpret_cast<const float4*>(X) + (size_t)j0 * 32;
    for (int i = tid; i < 1024; i += 256) Xs4[i] = Xg[i];
    __syncthreads();

    int n = tid & 127, half = tid >> 7;
    float acc[16];
    #pragma unroll
    for (int jj = 0; jj < 16; jj++) acc[jj] = 0.f;

    const float4* Wr = reinterpret_cast<const float4*>(W) + (size_t)n * 32;
    #pragma unroll 4
    for (int c4 = 0; c4 < 32; c4++) {
        float4 w = __ldg(Wr + c4);
        #pragma unroll
        for (int jj = 0; jj < 16; jj++) {
            float4 x = Xs4[(half * 16 + jj) * 32 + c4];
            acc[jj] += x.x * w.x + x.y * w.y + x.z * w.z + x.w * w.w;
        }
    }
    #pragma unroll
    for (int jj = 0; jj < 16; jj++) {
        int j = j0 + half * 16 + jj;
        float z = g_dis[j] * acc[jj];
        unsigned zb;
        asm("cvt.rna.tf32.f32 %0, %1;" : "=r"(zb) : "f"(z));
        float zf = __uint_as_float(zb);
        T[n][half * 16 + jj] = zf;
        g_z[(size_t)j * DIM + n] = zf;      // k-major (coalesced over n)
    }
    __syncthreads();
    #pragma unroll
    for (int it = 0; it < 4; it++) {
        int idx = it * 256 + tid;
        int nn = idx >> 3, j4 = idx & 7;
        float4 v = make_float4(T[nn][j4 * 4], T[nn][j4 * 4 + 1], T[nn][j4 * 4 + 2], T[nn][j4 * 4 + 3]);
        *reinterpret_cast<float4*>(&g_zt[(size_t)nn * NROWS + j0 + j4 * 4]) = v;
    }
}

// ===================== kernel 3: split-K GEMM, 256x128 block, 64x64 warp tiles =====================
#define BM 256
#define BK 32
#define STG 4
#define ASTR 36
#define BSTR 36
#define ASTG (BM * ASTR)              // 9216 floats
#define BSTG (DIM * BSTR)             // 4608 floats
#define SMEM_BYTES (STG * (ASTG + BSTG) * 4)   // 221184 B

static __device__ __forceinline__ void mma_tf32(float* c, const uint32_t* a, const uint32_t* b) {
    asm volatile(
        "mma.sync.aligned.m16n8k8.row.col.f32.tf32.tf32.f32 "
        "{%0,%1,%2,%3}, {%4,%5,%6,%7}, {%8,%9}, {%0,%1,%2,%3};"
        : "+f"(c[0]), "+f"(c[1]), "+f"(c[2]), "+f"(c[3])
        : "r"(a[0]), "r"(a[1]), "r"(a[2]), "r"(a[3]), "r"(b[0]), "r"(b[1]));
}

static __device__ __forceinline__ void ldsm4(uint32_t* r, uint32_t addr) {
    asm volatile("ldmatrix.sync.aligned.m8n8.x4.shared.b16 {%0,%1,%2,%3}, [%4];"
                 : "=r"(r[0]), "=r"(r[1]), "=r"(r[2]), "=r"(r[3]) : "r"(addr));
}

__global__ void __launch_bounds__(256, 1) gemm_kernel(const float* __restrict__ A) {
    extern __shared__ float sm[];
    float* sA = sm;                   // [STG][ASTG] A: 256 m-rows x BK k
    float* sB = sm + STG * ASTG;      // [STG][BSTG] B: 128 n-rows x BK k (g_zt layout)

    int tid = threadIdx.x, wid = tid >> 5, lane = tid & 31;
    int gid = lane >> 2, tig = lane & 3;
    const int m0 = blockIdx.x * BM;
    const int kbase = blockIdx.y * KSLICE;

    // 8 warps: 4 m-groups x 2 n-groups; warp tile 64x64
    const int wm0 = (wid >> 1) * 64, wn0 = (wid & 1) * 64;

    float acc[4][8][4];
    #pragma unroll
    for (int mf = 0; mf < 4; mf++)
        #pragma unroll
        for (int nf = 0; nf < 8; nf++)
            #pragma unroll
            for (int q = 0; q < 4; q++) acc[mf][nf][q] = 0.f;

    const int lrow = lane & 15;
    const int ksel = (lane >> 4) * 4;

    auto issue = [&](int stage, int buf) {
        int kk = kbase + stage * BK;
        #pragma unroll
        for (int it = 0; it < 8; it++) {               // A: 256 rows x 8 float4 = 2048
            int idx = it * 256 + tid;
            int r = idx >> 3, c4 = idx & 7;
            const float* gp = A + (size_t)(m0 + r) * NROWS + kk + c4 * 4;
            uint32_t sa = s2u(sA + buf * ASTG + r * ASTR + c4 * 4);
            asm volatile("cp.async.cg.shared.global [%0], [%1], 16;" :: "r"(sa), "l"(gp));
        }
        #pragma unroll
        for (int it = 0; it < 4; it++) {               // B: 128 n-rows x 8 float4 = 1024
            int idx = it * 256 + tid;
            int r = idx >> 3, c4 = idx & 7;
            const float* gp = g_zt + (size_t)r * NROWS + kk + c4 * 4;
            uint32_t sb = s2u(sB + buf * BSTG + r * BSTR + c4 * 4);
            asm volatile("cp.async.cg.shared.global [%0], [%1], 16;" :: "r"(sb), "l"(gp));
        }
        asm volatile("cp.async.commit_group;");
    };

    #pragma unroll
    for (int s = 0; s < STG - 1; s++) issue(s, s);

    const int NS = KSLICE / BK;  // 64
    for (int i = 0; i < NS; i++) {
        asm volatile("cp.async.wait_group %0;" :: "n"(STG - 2));
        __syncthreads();
        if (i + STG - 1 < NS) issue(i + STG - 1, (i + STG - 1) & (STG - 1));

        uint32_t a_s = s2u(sA + (i & (STG - 1)) * ASTG);
        uint32_t b_s = s2u(sB + (i & (STG - 1)) * BSTG);

        #pragma unroll
        for (int ks = 0; ks < BK / 8; ks++) {
            int k0 = ks * 8;
            uint32_t ar[4][4], br[4][4];
            #pragma unroll
            for (int mf = 0; mf < 4; mf++)
                ldsm4(ar[mf], a_s + 4u * ((wm0 + mf * 16 + lrow) * ASTR + k0 + ksel));
            #pragma unroll
            for (int p = 0; p < 4; p++)
                ldsm4(br[p], b_s + 4u * ((wn0 + p * 16 + lrow) * BSTR + k0 + ksel));
            #pragma unroll
            for (int mf = 0; mf < 4; mf++)
                #pragma unroll
                for (int p = 0; p < 4; p++) {
                    uint32_t b0[2] = {br[p][0], br[p][2]};
                    uint32_t b1[2] = {br[p][1], br[p][3]};
                    mma_tf32(acc[mf][2 * p], ar[mf], b0);
                    mma_tf32(acc[mf][2 * p + 1], ar[mf], b1);
                }
        }
    }

    // write split-K partials
    float* P = g_part[blockIdx.y];
    #pragma unroll
    for (int mf = 0; mf < 4; mf++) {
        int r0 = m0 + wm0 + mf * 16 + gid;
        #pragma unroll
        for (int nf = 0; nf < 8; nf++) {
            int c = wn0 + nf * 8 + 2 * tig;
            *reinterpret_cast<float2*>(&P[(size_t)r0 * DIM + c]) =
                make_float2(acc[mf][nf][0], acc[mf][nf][1]);
            *reinterpret_cast<float2*>(&P[(size_t)(r0 + 8) * DIM + c]) =
                make_float2(acc[mf][nf][2], acc[mf][nf][3]);
        }
    }
}

// ===================== kernel 4: out = dis .* (sum P + G) + b =====================
__global__ void __launch_bounds__(256) reduce_kernel(const float* __restrict__ bias,
                                                     float* __restrict__ out) {
    int idx = blockIdx.x * 256 + threadIdx.x;     // float4 index
    int row = idx >> 5, n4 = idx & 31;
    float4 a = reinterpret_cast<const float4*>(g_part[0])[idx];
    float4 b1 = reinterpret_cast<const float4*>(g_part[1])[idx];
    float4 c = reinterpret_cast<const float4*>(g_part[2])[idx];
    float4 e = reinterpret_cast<const float4*>(g_part[3])[idx];
    float4 g = reinterpret_cast<const float4*>(g_z)[idx];
    float d = g_dis[row];
    float4 bb = __ldg(reinterpret_cast<const float4*>(bias) + n4);
    float4 o;
    o.x = d * (a.x + b1.x + c.x + e.x + g.x) + bb.x;
    o.y = d * (a.y + b1.y + c.y + e.y + g.y) + bb.y;
    o.z = d * (a.z + b1.z + c.z + e.z + g.z) + bb.z;
    o.w = d * (a.w + b1.w + c.w + e.w + g.w) + bb.w;
    reinterpret_cast<float4*>(out)[idx] = o;
}

// ===================== host =====================
extern "C" void kernel_launch(void* const* d_in, const int* in_sizes, int n_in,
                              void* d_out, int out_size) {
    const float* X = (const float*)d_in[0];
    const float* A = (const float*)d_in[1];
    const float* W = (const float*)d_in[2];
    const float* b = (const float*)d_in[3];
    float* out = (float*)d_out;

    rowsum_kernel<<<NROWS, 256>>>((const float4*)A);
    z_kernel<<<NROWS / 32, 256>>>(X, W);

    cudaFuncSetAttribute(gemm_kernel, cudaFuncAttributeMaxDynamicSharedMemorySize, SMEM_BYTES);
    gemm_kernel<<<dim3(NROWS / BM, KSPLIT), 256, SMEM_BYTES>>>(A);
    reduce_kernel<<<NROWS * DIM / 4 / 256, 256>>>(b, out);
}

// round 8
// speedup vs baseline: 3.2301x; 1.1813x over previous
#include <cuda_runtime.h>
#include <cuda_fp16.h>
#include <cstdint>

#define NROWS 8192
#define DIM 128
#define KSPLIT 4
#define KSLICE (NROWS / KSPLIT)   // 2048

__device__ float g_dis[NROWS];
__device__ __half g_ah[(size_t)NROWS * NROWS];        // A in fp16
__device__ float g_z[(size_t)NROWS * DIM];            // G fp32 k-major (reduce)
__device__ __half g_zt[(size_t)DIM * NROWS];          // G^T fp16 n-major (GEMM B)
__device__ float g_part[KSPLIT][(size_t)NROWS * DIM];

static __device__ __forceinline__ uint32_t s2u(const void* p) {
    uint32_t a;
    asm("{ .reg .u64 t; cvta.to.shared.u64 t, %1; cvt.u32.u64 %0, t; }" : "=r"(a) : "l"(p));
    return a;
}

// ===================== kernel 1: row sums -> dis, and A -> fp16 =====================
__global__ void __launch_bounds__(256) rowsum_kernel(const float4* __restrict__ A4) {
    int row = blockIdx.x;
    const float4* r = A4 + (size_t)row * (NROWS / 4);
    uint2* ah = reinterpret_cast<uint2*>(g_ah) + (size_t)row * (NROWS / 4);
    float s = 0.f;
    #pragma unroll
    for (int p = 0; p < 8; p++) {
        float4 v = __ldcs(r + threadIdx.x + p * 256);
        s += (v.x + v.y) + (v.z + v.w);
        __half2 h0 = __floats2half2_rn(v.x, v.y);
        __half2 h1 = __floats2half2_rn(v.z, v.w);
        uint2 pk;
        pk.x = *reinterpret_cast<uint32_t*>(&h0);
        pk.y = *reinterpret_cast<uint32_t*>(&h1);
        __stcs(ah + threadIdx.x + p * 256, pk);
    }
    #pragma unroll
    for (int o = 16; o; o >>= 1) s += __shfl_xor_sync(0xffffffffu, s, o);
    __shared__ float ws[8];
    if ((threadIdx.x & 31) == 0) ws[threadIdx.x >> 5] = s;
    __syncthreads();
    if (threadIdx.x < 8) {
        float t = ws[threadIdx.x];
        #pragma unroll
        for (int o = 4; o; o >>= 1) t += __shfl_xor_sync(0xffu, t, o);
        if (threadIdx.x == 0) g_dis[row] = rsqrtf(t + 1.0f);
    }
}

// ===================== kernel 2: G = dis.*(X W^T): g_z fp32 + g_zt fp16 n-major =====================
__global__ void __launch_bounds__(256) z_kernel(const float* __restrict__ X,
                                                const float* __restrict__ W) {
    __shared__ float4 Xs4[32 * 32];
    __shared__ float T[128][33];
    int tid = threadIdx.x;
    int j0 = blockIdx.x * 32;
    const float4* Xg = reinterpret_cast<const float4*>(X) + (size_t)j0 * 32;
    for (int i = tid; i < 1024; i += 256) Xs4[i] = Xg[i];
    __syncthreads();

    int n = tid & 127, half = tid >> 7;
    float acc[16];
    #pragma unroll
    for (int jj = 0; jj < 16; jj++) acc[jj] = 0.f;

    const float4* Wr = reinterpret_cast<const float4*>(W) + (size_t)n * 32;
    #pragma unroll 4
    for (int c4 = 0; c4 < 32; c4++) {
        float4 w = __ldg(Wr + c4);
        #pragma unroll
        for (int jj = 0; jj < 16; jj++) {
            float4 x = Xs4[(half * 16 + jj) * 32 + c4];
            acc[jj] += x.x * w.x + x.y * w.y + x.z * w.z + x.w * w.w;
        }
    }
    #pragma unroll
    for (int jj = 0; jj < 16; jj++) {
        int j = j0 + half * 16 + jj;
        float z = g_dis[j] * acc[jj];
        T[n][half * 16 + jj] = z;
        g_z[(size_t)j * DIM + n] = z;
    }
    __syncthreads();
    #pragma unroll
    for (int it = 0; it < 4; it++) {
        int idx = it * 256 + tid;
        int nn = idx >> 3, j4 = idx & 7;
        __half2 h0 = __floats2half2_rn(T[nn][j4 * 4], T[nn][j4 * 4 + 1]);
        __half2 h1 = __floats2half2_rn(T[nn][j4 * 4 + 2], T[nn][j4 * 4 + 3]);
        uint2 pk;
        pk.x = *reinterpret_cast<uint32_t*>(&h0);
        pk.y = *reinterpret_cast<uint32_t*>(&h1);
        *reinterpret_cast<uint2*>(&g_zt[(size_t)nn * NROWS + j0 + j4 * 4]) = pk;
    }
}

// ===================== kernel 3: split-K fp16 GEMM, 256x128 block, 64x64 warp tiles =====================
#define BM 256
#define BK 32
#define STG 4
#define ASTR 40                        // halves per row (80 B): ldsm phases hit all 32 banks
#define BSTR 40
#define ASTG (BM * ASTR)
#define BSTG (DIM * BSTR)
#define SMEM_BYTES (STG * (ASTG + BSTG) * 2)   // 122880 B

static __device__ __forceinline__ void mma_f16(float* c, const uint32_t* a, const uint32_t* b) {
    asm volatile(
        "mma.sync.aligned.m16n8k16.row.col.f32.f16.f16.f32 "
        "{%0,%1,%2,%3}, {%4,%5,%6,%7}, {%8,%9}, {%0,%1,%2,%3};"
        : "+f"(c[0]), "+f"(c[1]), "+f"(c[2]), "+f"(c[3])
        : "r"(a[0]), "r"(a[1]), "r"(a[2]), "r"(a[3]), "r"(b[0]), "r"(b[1]));
}

static __device__ __forceinline__ void ldsm4(uint32_t* r, uint32_t addr) {
    asm volatile("ldmatrix.sync.aligned.m8n8.x4.shared.b16 {%0,%1,%2,%3}, [%4];"
                 : "=r"(r[0]), "=r"(r[1]), "=r"(r[2]), "=r"(r[3]) : "r"(addr));
}

__global__ void __launch_bounds__(256, 1) gemm_kernel() {
    extern __shared__ __half sm[];
    __half* sA = sm;                   // [STG][ASTG] A: 256 m-rows x 32 k
    __half* sB = sm + STG * ASTG;      // [STG][BSTG] B: 128 n-rows x 32 k

    int tid = threadIdx.x, wid = tid >> 5, lane = tid & 31;
    int gid = lane >> 2, tig = lane & 3;
    const int m0 = blockIdx.x * BM;
    const int kbase = blockIdx.y * KSLICE;

    const int wm0 = (wid >> 1) * 64, wn0 = (wid & 1) * 64;  // 4x2 warps, 64x64 tiles

    float acc[4][8][4];
    #pragma unroll
    for (int mf = 0; mf < 4; mf++)
        #pragma unroll
        for (int nf = 0; nf < 8; nf++)
            #pragma unroll
            for (int q = 0; q < 4; q++) acc[mf][nf][q] = 0.f;

    const int a_row = lane & 15;
    const uint32_t a_koff = (uint32_t)(lane >> 4) * 16;      // bytes
    const int b_row = (lane & 7) | ((lane >> 4) << 3);
    const uint32_t b_koff = (uint32_t)((lane >> 3) & 1) * 16;

    auto issue = [&](int stage, int buf) {
        int kk = kbase + stage * BK;
        #pragma unroll
        for (int it = 0; it < 4; it++) {               // A: 1024 x 16B chunks
            int idx = it * 256 + tid;
            int r = idx >> 2, c = idx & 3;
            const __half* gp = g_ah + (size_t)(m0 + r) * NROWS + kk + c * 8;
            uint32_t sa = s2u(sA + buf * ASTG + r * ASTR + c * 8);
            asm volatile("cp.async.cg.shared.global [%0], [%1], 16;" :: "r"(sa), "l"(gp));
        }
        #pragma unroll
        for (int it = 0; it < 2; it++) {               // B: 512 x 16B chunks
            int idx = it * 256 + tid;
            int r = idx >> 2, c = idx & 3;
            const __half* gp = g_zt + (size_t)r * NROWS + kk + c * 8;
            uint32_t sb = s2u(sB + buf * BSTG + r * BSTR + c * 8);
            asm volatile("cp.async.cg.shared.global [%0], [%1], 16;" :: "r"(sb), "l"(gp));
        }
        asm volatile("cp.async.commit_group;");
    };

    #pragma unroll
    for (int s = 0; s < STG - 1; s++) issue(s, s);

    const int NS = KSLICE / BK;  // 64
    for (int i = 0; i < NS; i++) {
        asm volatile("cp.async.wait_group %0;" :: "n"(STG - 2));
        __syncthreads();
        if (i + STG - 1 < NS) issue(i + STG - 1, (i + STG - 1) & (STG - 1));

        uint32_t a_s = s2u(sA + (i & (STG - 1)) * ASTG);
        uint32_t b_s = s2u(sB + (i & (STG - 1)) * BSTG);

        #pragma unroll
        for (int ks = 0; ks < 2; ks++) {               // 2 x k16
            uint32_t k0h = ks * 16;
            uint32_t ar[4][4], br[4][4];
            #pragma unroll
            for (int mf = 0; mf < 4; mf++)             // A m16 x k16 tiles
                ldsm4(ar[mf], a_s + 2u * ((wm0 + mf * 16 + a_row) * ASTR + k0h) + a_koff);
            #pragma unroll
            for (int t = 0; t < 4; t++)                // B n16 x k16 tiles (n = wn0 + 16t)
                ldsm4(br[t], b_s + 2u * ((wn0 + t * 16 + b_row) * BSTR + k0h) + b_koff);
            #pragma unroll
            for (int mf = 0; mf < 4; mf++)
                #pragma unroll
                for (int t = 0; t < 4; t++) {
                    uint32_t bt0[2] = {br[t][0], br[t][1]};   // n = wn0+16t .. +7
                    uint32_t bt1[2] = {br[t][2], br[t][3]};   // n = wn0+16t+8 .. +15
                    mma_f16(acc[mf][2 * t], ar[mf], bt0);
                    mma_f16(acc[mf][2 * t + 1], ar[mf], bt1);
                }
        }
    }

    // split-K partials; acc[mf][nf] covers n = wn0 + nf*8
    float* P = g_part[blockIdx.y];
    #pragma unroll
    for (int mf = 0; mf < 4; mf++) {
        int r0 = m0 + wm0 + mf * 16 + gid;
        #pragma unroll
        for (int nf = 0; nf < 8; nf++) {
            int c = wn0 + nf * 8 + 2 * tig;
            *reinterpret_cast<float2*>(&P[(size_t)r0 * DIM + c]) =
                make_float2(acc[mf][nf][0], acc[mf][nf][1]);
            *reinterpret_cast<float2*>(&P[(size_t)(r0 + 8) * DIM + c]) =
                make_float2(acc[mf][nf][2], acc[mf][nf][3]);
        }
    }
}

// ===================== kernel 4: out = dis .* (sum P + G) + b =====================
__global__ void __launch_bounds__(256) reduce_kernel(const float* __restrict__ bias,
                                                     float* __restrict__ out) {
    int idx = blockIdx.x * 256 + threadIdx.x;
    int row = idx >> 5, n4 = idx & 31;
    float4 a = reinterpret_cast<const float4*>(g_part[0])[idx];
    float4 b1 = reinterpret_cast<const float4*>(g_part[1])[idx];
    float4 c = reinterpret_cast<const float4*>(g_part[2])[idx];
    float4 e = reinterpret_cast<const float4*>(g_part[3])[idx];
    float4 g = reinterpret_cast<const float4*>(g_z)[idx];
    float d = g_dis[row];
    float4 bb = __ldg(reinterpret_cast<const float4*>(bias) + n4);
    float4 o;
    o.x = d * (a.x + b1.x + c.x + e.x + g.x) + bb.x;
    o.y = d * (a.y + b1.y + c.y + e.y + g.y) + bb.y;
    o.z = d * (a.z + b1.z + c.z + e.z + g.z) + bb.z;
    o.w = d * (a.w + b1.w + c.w + e.w + g.w) + bb.w;
    reinterpret_cast<float4*>(out)[idx] = o;
}

// ===================== host =====================
extern "C" void kernel_launch(void* const* d_in, const int* in_sizes, int n_in,
                              void* d_out, int out_size) {
    const float* X = (const float*)d_in[0];
    const float* A = (const float*)d_in[1];
    const float* W = (const float*)d_in[2];
    const float* b = (const float*)d_in[3];
    float* out = (float*)d_out;

    rowsum_kernel<<<NROWS, 256>>>((const float4*)A);
    z_kernel<<<NROWS / 32, 256>>>(X, W);

    cudaFuncSetAttribute(gemm_kernel, cudaFuncAttributeMaxDynamicSharedMemorySize, SMEM_BYTES);
    gemm_kernel<<<dim3(NROWS / BM, KSPLIT), 256, SMEM_BYTES>>>();
    reduce_kernel<<<NROWS * DIM / 4 / 256, 256>>>(b, out);
}

// round 9
// speedup vs baseline: 3.4142x; 1.0570x over previous
#include <cuda_runtime.h>
#include <cuda_fp16.h>
#include <cstdint>

#define NROWS 8192
#define DIM 128
#define KSPLIT 4
#define KSLICE (NROWS / KSPLIT)   // 2048

__device__ float g_dis[NROWS];
__device__ __half g_ah[(size_t)NROWS * NROWS];        // A in fp16
__device__ float g_z[(size_t)NROWS * DIM];            // G fp32 k-major (reduce)
__device__ __half g_zt[(size_t)DIM * NROWS];          // G^T fp16 n-major (GEMM B)
__device__ float g_part[KSPLIT][(size_t)NROWS * DIM];

static __device__ __forceinline__ uint32_t s2u(const void* p) {
    uint32_t a;
    asm("{ .reg .u64 t; cvta.to.shared.u64 t, %1; cvt.u32.u64 %0, t; }" : "=r"(a) : "l"(p));
    return a;
}

// ===================== kernel 1: row sums -> dis, and A -> fp16 =====================
__global__ void __launch_bounds__(256) rowsum_kernel(const float4* __restrict__ A4) {
    int row = blockIdx.x;
    const float4* r = A4 + (size_t)row * (NROWS / 4);
    uint2* ah = reinterpret_cast<uint2*>(g_ah) + (size_t)row * (NROWS / 4);
    float s = 0.f;
    #pragma unroll
    for (int p = 0; p < 8; p++) {
        float4 v = __ldcs(r + threadIdx.x + p * 256);
        s += (v.x + v.y) + (v.z + v.w);
        __half2 h0 = __floats2half2_rn(v.x, v.y);
        __half2 h1 = __floats2half2_rn(v.z, v.w);
        uint2 pk;
        pk.x = *reinterpret_cast<uint32_t*>(&h0);
        pk.y = *reinterpret_cast<uint32_t*>(&h1);
        __stcs(ah + threadIdx.x + p * 256, pk);
    }
    #pragma unroll
    for (int o = 16; o; o >>= 1) s += __shfl_xor_sync(0xffffffffu, s, o);
    __shared__ float ws[8];
    if ((threadIdx.x & 31) == 0) ws[threadIdx.x >> 5] = s;
    __syncthreads();
    if (threadIdx.x < 8) {
        float t = ws[threadIdx.x];
        #pragma unroll
        for (int o = 4; o; o >>= 1) t += __shfl_xor_sync(0xffu, t, o);
        if (threadIdx.x == 0) g_dis[row] = rsqrtf(t + 1.0f);
    }
}

// ===================== kernel 2: G = dis.*(X W^T): g_z fp32 + g_zt fp16 n-major =====================
__global__ void __launch_bounds__(256) z_kernel(const float* __restrict__ X,
                                                const float* __restrict__ W) {
    __shared__ float4 Xs4[32 * 32];
    __shared__ float T[128][33];
    int tid = threadIdx.x;
    int j0 = blockIdx.x * 32;
    const float4* Xg = reinterpret_cast<const float4*>(X) + (size_t)j0 * 32;
    for (int i = tid; i < 1024; i += 256) Xs4[i] = Xg[i];
    __syncthreads();

    int n = tid & 127, half = tid >> 7;
    float acc[16];
    #pragma unroll
    for (int jj = 0; jj < 16; jj++) acc[jj] = 0.f;

    const float4* Wr = reinterpret_cast<const float4*>(W) + (size_t)n * 32;
    #pragma unroll 4
    for (int c4 = 0; c4 < 32; c4++) {
        float4 w = __ldg(Wr + c4);
        #pragma unroll
        for (int jj = 0; jj < 16; jj++) {
            float4 x = Xs4[(half * 16 + jj) * 32 + c4];
            acc[jj] += x.x * w.x + x.y * w.y + x.z * w.z + x.w * w.w;
        }
    }
    #pragma unroll
    for (int jj = 0; jj < 16; jj++) {
        int j = j0 + half * 16 + jj;
        float z = g_dis[j] * acc[jj];
        T[n][half * 16 + jj] = z;
        g_z[(size_t)j * DIM + n] = z;
    }
    __syncthreads();
    #pragma unroll
    for (int it = 0; it < 4; it++) {
        int idx = it * 256 + tid;
        int nn = idx >> 3, j4 = idx & 7;
        __half2 h0 = __floats2half2_rn(T[nn][j4 * 4], T[nn][j4 * 4 + 1]);
        __half2 h1 = __floats2half2_rn(T[nn][j4 * 4 + 2], T[nn][j4 * 4 + 3]);
        uint2 pk;
        pk.x = *reinterpret_cast<uint32_t*>(&h0);
        pk.y = *reinterpret_cast<uint32_t*>(&h1);
        *reinterpret_cast<uint2*>(&g_zt[(size_t)nn * NROWS + j0 + j4 * 4]) = pk;
    }
}

// ===================== kernel 3: split-K fp16 GEMM, BK=64, frag double-buffer =====================
#define BM 256
#define BK 64
#define STG 3
#define ASTR 72                        // halves per row (144 B, 16B-aligned, ldsm conflict-free)
#define BSTR 72
#define ASTG (BM * ASTR)               // 18432 halves
#define BSTG (DIM * BSTR)              // 9216 halves
#define SMEM_BYTES (STG * (ASTG + BSTG) * 2)   // 165888 B

static __device__ __forceinline__ void mma_f16(float* c, const uint32_t* a, const uint32_t* b) {
    asm volatile(
        "mma.sync.aligned.m16n8k16.row.col.f32.f16.f16.f32 "
        "{%0,%1,%2,%3}, {%4,%5,%6,%7}, {%8,%9}, {%0,%1,%2,%3};"
        : "+f"(c[0]), "+f"(c[1]), "+f"(c[2]), "+f"(c[3])
        : "r"(a[0]), "r"(a[1]), "r"(a[2]), "r"(a[3]), "r"(b[0]), "r"(b[1]));
}

static __device__ __forceinline__ void ldsm4(uint32_t* r, uint32_t addr) {
    asm volatile("ldmatrix.sync.aligned.m8n8.x4.shared.b16 {%0,%1,%2,%3}, [%4];"
                 : "=r"(r[0]), "=r"(r[1]), "=r"(r[2]), "=r"(r[3]) : "r"(addr));
}

__global__ void __launch_bounds__(256, 1) gemm_kernel() {
    extern __shared__ __half sm[];
    __half* sA = sm;                   // [STG][ASTG] A: 256 m-rows x 64 k
    __half* sB = sm + STG * ASTG;      // [STG][BSTG] B: 128 n-rows x 64 k

    int tid = threadIdx.x, wid = tid >> 5, lane = tid & 31;
    int gid = lane >> 2, tig = lane & 3;
    const int m0 = blockIdx.x * BM;
    const int kbase = blockIdx.y * KSLICE;

    const int wm0 = (wid >> 1) * 64, wn0 = (wid & 1) * 64;  // 4x2 warps, 64x64 tiles

    float acc[4][8][4];
    #pragma unroll
    for (int mf = 0; mf < 4; mf++)
        #pragma unroll
        for (int nf = 0; nf < 8; nf++)
            #pragma unroll
            for (int q = 0; q < 4; q++) acc[mf][nf][q] = 0.f;

    const int a_row = lane & 15;
    const uint32_t a_koff = (uint32_t)(lane >> 4) * 16;      // bytes
    const int b_row = (lane & 7) | ((lane >> 4) << 3);
    const uint32_t b_koff = (uint32_t)((lane >> 3) & 1) * 16;

    auto issue = [&](int stage, int buf) {
        int kk = kbase + stage * BK;
        #pragma unroll
        for (int it = 0; it < 8; it++) {               // A: 256 rows x 8 chunks(16B) = 2048
            int idx = it * 256 + tid;
            int r = idx >> 3, c = idx & 7;
            const __half* gp = g_ah + (size_t)(m0 + r) * NROWS + kk + c * 8;
            uint32_t sa = s2u(sA + buf * ASTG + r * ASTR + c * 8);
            asm volatile("cp.async.cg.shared.global [%0], [%1], 16;" :: "r"(sa), "l"(gp));
        }
        #pragma unroll
        for (int it = 0; it < 4; it++) {               // B: 128 rows x 8 chunks = 1024
            int idx = it * 256 + tid;
            int r = idx >> 3, c = idx & 7;
            const __half* gp = g_zt + (size_t)r * NROWS + kk + c * 8;
            uint32_t sb = s2u(sB + buf * BSTG + r * BSTR + c * 8);
            asm volatile("cp.async.cg.shared.global [%0], [%1], 16;" :: "r"(sb), "l"(gp));
        }
        asm volatile("cp.async.commit_group;");
    };

    #pragma unroll
    for (int s = 0; s < STG - 1; s++) issue(s, s);

    const int NS = KSLICE / BK;  // 32
    int buf = 0;
    for (int i = 0; i < NS; i++) {
        asm volatile("cp.async.wait_group %0;" :: "n"(STG - 2));
        __syncthreads();
        if (i + STG - 1 < NS) issue(i + STG - 1, (i + STG - 1) % STG);

        uint32_t a_s = s2u(sA + buf * ASTG);
        uint32_t b_s = s2u(sB + buf * BSTG);
        buf = (buf + 1 == STG) ? 0 : buf + 1;

        // fragment double-buffer over 4 k16 steps
        uint32_t ar[2][4][4], br[2][4][4];
        #pragma unroll
        for (int mf = 0; mf < 4; mf++)
            ldsm4(ar[0][mf], a_s + 2u * ((wm0 + mf * 16 + a_row) * ASTR) + a_koff);
        #pragma unroll
        for (int t = 0; t < 4; t++)
            ldsm4(br[0][t], b_s + 2u * ((wn0 + t * 16 + b_row) * BSTR) + b_koff);

        #pragma unroll
        for (int ks = 0; ks < 4; ks++) {
            int cur = ks & 1, nxt = cur ^ 1;
            if (ks < 3) {
                uint32_t k1h = (ks + 1) * 16;
                #pragma unroll
                for (int mf = 0; mf < 4; mf++)
                    ldsm4(ar[nxt][mf], a_s + 2u * ((wm0 + mf * 16 + a_row) * ASTR + k1h) + a_koff);
                #pragma unroll
                for (int t = 0; t < 4; t++)
                    ldsm4(br[nxt][t], b_s + 2u * ((wn0 + t * 16 + b_row) * BSTR + k1h) + b_koff);
            }
            #pragma unroll
            for (int mf = 0; mf < 4; mf++)
                #pragma unroll
                for (int t = 0; t < 4; t++) {
                    uint32_t bt0[2] = {br[cur][t][0], br[cur][t][1]};
                    uint32_t bt1[2] = {br[cur][t][2], br[cur][t][3]};
                    mma_f16(acc[mf][2 * t], ar[cur][mf], bt0);
                    mma_f16(acc[mf][2 * t + 1], ar[cur][mf], bt1);
                }
        }
    }

    // split-K partials; acc[mf][nf] covers n = wn0 + nf*8
    float* P = g_part[blockIdx.y];
    #pragma unroll
    for (int mf = 0; mf < 4; mf++) {
        int r0 = m0 + wm0 + mf * 16 + gid;
        #pragma unroll
        for (int nf = 0; nf < 8; nf++) {
            int c = wn0 + nf * 8 + 2 * tig;
            *reinterpret_cast<float2*>(&P[(size_t)r0 * DIM + c]) =
                make_float2(acc[mf][nf][0], acc[mf][nf][1]);
            *reinterpret_cast<float2*>(&P[(size_t)(r0 + 8) * DIM + c]) =
                make_float2(acc[mf][nf][2], acc[mf][nf][3]);
        }
    }
}

// ===================== kernel 4: out = dis .* (sum P + G) + b =====================
__global__ void __launch_bounds__(256) reduce_kernel(const float* __restrict__ bias,
                                                     float* __restrict__ out) {
    int idx = blockIdx.x * 256 + threadIdx.x;
    int row = idx >> 5, n4 = idx & 31;
    float4 a = reinterpret_cast<const float4*>(g_part[0])[idx];
    float4 b1 = reinterpret_cast<const float4*>(g_part[1])[idx];
    float4 c = reinterpret_cast<const float4*>(g_part[2])[idx];
    float4 e = reinterpret_cast<const float4*>(g_part[3])[idx];
    float4 g = reinterpret_cast<const float4*>(g_z)[idx];
    float d = g_dis[row];
    float4 bb = __ldg(reinterpret_cast<const float4*>(bias) + n4);
    float4 o;
    o.x = d * (a.x + b1.x + c.x + e.x + g.x) + bb.x;
    o.y = d * (a.y + b1.y + c.y + e.y + g.y) + bb.y;
    o.z = d * (a.z + b1.z + c.z + e.z + g.z) + bb.z;
    o.w = d * (a.w + b1.w + c.w + e.w + g.w) + bb.w;
    reinterpret_cast<float4*>(out)[idx] = o;
}

// ===================== host =====================
extern "C" void kernel_launch(void* const* d_in, const int* in_sizes, int n_in,
                              void* d_out, int out_size) {
    const float* X = (const float*)d_in[0];
    const float* A = (const float*)d_in[1];
    const float* W = (const float*)d_in[2];
    const float* b = (const float*)d_in[3];
    float* out = (float*)d_out;

    rowsum_kernel<<<NROWS, 256>>>((const float4*)A);
    z_kernel<<<NROWS / 32, 256>>>(X, W);

    cudaFuncSetAttribute(gemm_kernel, cudaFuncAttributeMaxDynamicSharedMemorySize, SMEM_BYTES);
    gemm_kernel<<<dim3(NROWS / BM, KSPLIT), 256, SMEM_BYTES>>>();
    reduce_kernel<<<NROWS * DIM / 4 / 256, 256>>>(b, out);
}